// round 15
// baseline (speedup 1.0000x reference)
#include <cuda_runtime.h>
#include <cuda_bf16.h>
#include <math.h>
#include <stdint.h>

// Problem constants (fixed shapes)
#define SRC_LEN 512
#define BSZ     16
#define SNT_LEN 512
#define E_DIM   512
#define C_DIM   512
#define V_DIM   12000
#define EXT_DIM 500
#define TOT_DIM (V_DIM + EXT_DIM)       // 12500
#define M_ROWS  (SRC_LEN * BSZ)         // 8192
#define LL_ELEMS ((size_t)M_ROWS * TOT_DIM)
#define LOG_EPS (-27.6310211159f)       // log(1e-12)

// Scratch (device globals — no allocations allowed)
__device__ __nv_bfloat16 g_concept_bf[(size_t)M_ROWS * E_DIM];
__device__ __nv_bfloat16 g_Wt_bf[(size_t)C_DIM * E_DIM];
__device__ __nv_bfloat16 g_h_bf[(size_t)M_ROWS * C_DIM];
__device__ __nv_bfloat16 g_Wg_bf[(size_t)V_DIM * C_DIM];
__device__ __nv_bfloat16 g_logit_bf[(size_t)M_ROWS * V_DIM];  // bf16 logits
__device__ float g_graw[M_ROWS * 3];    // raw gate logits (pre-softmax, no bias)
__device__ float g_rowsum[M_ROWS];      // sum of exp(logits) per row

#define GK   512
#define BK   64
#define NKT  (GK / BK)            // 8
#define ROWB 144                  // padded smem row stride (bytes)
#define STAGE_BYTES (128 * ROWB)  // 18432 per operand per stage (gemm1)
#define NSTAGE 3
#define GEMM_SMEM (NSTAGE * 2 * STAGE_BYTES)   // 110592
#define ROWB_STG 272              // epilogue staging stride (17*16)

// GEMM2 (256x128) smem layout
#define G2_A_STAGE (256 * ROWB)              // 36864
#define G2_B_STAGE (128 * ROWB)              // 18432
#define G2_STAGE   (G2_A_STAGE + G2_B_STAGE) // 55296
#define G2_SMEM    (NSTAGE * G2_STAGE)       // 165888

#define V4   (V_DIM / 4)      // 3000
#define T4   (TOT_DIM / 4)    // 3125
#define V8   (V_DIM / 8)      // 1500

__device__ __forceinline__ uint32_t smem_u32(const void* p) {
    uint32_t a;
    asm("{ .reg .u64 t; cvta.to.shared.u64 t, %1; cvt.u32.u64 %0, t; }"
        : "=r"(a) : "l"(p));
    return a;
}
__device__ __forceinline__ void cp16(uint32_t saddr, const void* gaddr, uint32_t srcsz) {
    asm volatile("cp.async.cg.shared.global [%0], [%1], 16, %2;"
                 :: "r"(saddr), "l"(gaddr), "r"(srcsz));
}
__device__ __forceinline__ void cp_commit() {
    asm volatile("cp.async.commit_group;");
}
template <int N>
__device__ __forceinline__ void cp_wait() {
    asm volatile("cp.async.wait_group %0;" :: "n"(N));
}
__device__ __forceinline__ void ldmx4(uint32_t addr, uint32_t& r0, uint32_t& r1,
                                      uint32_t& r2, uint32_t& r3) {
    asm volatile("ldmatrix.sync.aligned.m8n8.x4.shared.b16 {%0,%1,%2,%3}, [%4];"
                 : "=r"(r0), "=r"(r1), "=r"(r2), "=r"(r3) : "r"(addr));
}
__device__ __forceinline__ void mma16816(float& c0, float& c1, float& c2, float& c3,
                                         uint32_t a0, uint32_t a1, uint32_t a2, uint32_t a3,
                                         uint32_t b0, uint32_t b1) {
    asm volatile(
        "mma.sync.aligned.m16n8k16.row.col.f32.bf16.bf16.f32 "
        "{%0,%1,%2,%3}, {%4,%5,%6,%7}, {%8,%9}, {%0,%1,%2,%3};"
        : "+f"(c0), "+f"(c1), "+f"(c2), "+f"(c3)
        : "r"(a0), "r"(a1), "r"(a2), "r"(a3), "r"(b0), "r"(b1));
}

// ===========================================================================
// GEMM1 mainloop (128x128, 256 thr) — unchanged from R14
// ===========================================================================
#define GEMM_MAINLOOP(A_, B_, NGUARD)                                          \
    auto a_off = [&](int s) -> uint32_t { return sbase + s * 2 * STAGE_BYTES; };\
    auto b_off = [&](int s) -> uint32_t { return sbase + s * 2 * STAGE_BYTES + STAGE_BYTES; };\
    auto issue_stage = [&](int kt, int s) {                                    \
        const int k0 = kt * BK;                                                \
        _Pragma("unroll")                                                      \
        for (int u = 0; u < 4; u++) {                                          \
            int idx = tid + u * 256;                                           \
            int row = idx >> 3;                                                \
            int c   = idx & 7;                                                 \
            cp16(a_off(s) + row * ROWB + c * 16,                               \
                 A_ + (size_t)(m0 + row) * GK + k0 + c * 8, 16);               \
        }                                                                      \
        _Pragma("unroll")                                                      \
        for (int u = 0; u < 4; u++) {                                          \
            int idx = tid + u * 256;                                           \
            int row = idx >> 3;                                                \
            int c   = idx & 7;                                                 \
            int gr = n0 + row;                                                 \
            const void* ga = B_ + (size_t)(gr < NGUARD ? gr : NGUARD - 1) * GK + k0 + c * 8;\
            cp16(b_off(s) + row * ROWB + c * 16, ga, (gr < NGUARD) ? 16u : 0u);\
        }                                                                      \
        cp_commit();                                                           \
    };                                                                         \
    float acc[4][4][4];                                                        \
    _Pragma("unroll")                                                          \
    for (int i = 0; i < 4; i++)                                                \
        _Pragma("unroll")                                                      \
        for (int j = 0; j < 4; j++)                                            \
            _Pragma("unroll")                                                  \
            for (int e = 0; e < 4; e++) acc[i][j][e] = 0.f;                    \
    issue_stage(0, 0);                                                         \
    issue_stage(1, 1);                                                         \
    const int g    = lane >> 3;                                                \
    const int lrow = lane & 7;                                                 \
    _Pragma("unroll")                                                          \
    for (int kt = 0; kt < NKT; kt++) {                                         \
        const int s = kt % NSTAGE;                                             \
        if (kt + 2 < NKT) {                                                    \
            issue_stage(kt + 2, (kt + 2) % NSTAGE);                            \
            cp_wait<2>();                                                      \
        } else if (kt + 1 < NKT) {                                             \
            cp_wait<1>();                                                      \
        } else {                                                               \
            cp_wait<0>();                                                      \
        }                                                                      \
        __syncthreads();                                                       \
        const uint32_t abase = a_off(s);                                       \
        const uint32_t bbase = b_off(s);                                       \
        _Pragma("unroll")                                                      \
        for (int ks = 0; ks < 4; ks++) {                                       \
            uint32_t a[4][4];                                                  \
            _Pragma("unroll")                                                  \
            for (int mt = 0; mt < 4; mt++) {                                   \
                int row = warp_m * 64 + mt * 16 + lrow + (g & 1) * 8;          \
                int chunk = ks * 2 + (g >> 1);                                 \
                ldmx4(abase + row * ROWB + chunk * 16,                         \
                      a[mt][0], a[mt][1], a[mt][2], a[mt][3]);                 \
            }                                                                  \
            uint32_t b[4][2];                                                  \
            _Pragma("unroll")                                                  \
            for (int nt = 0; nt < 2; nt++) {                                   \
                int row = warp_n * 32 + nt * 16 + lrow + (g >> 1) * 8;         \
                int chunk = ks * 2 + (g & 1);                                  \
                uint32_t r0, r1, r2, r3;                                       \
                ldmx4(bbase + row * ROWB + chunk * 16, r0, r1, r2, r3);        \
                b[nt * 2 + 0][0] = r0; b[nt * 2 + 0][1] = r1;                  \
                b[nt * 2 + 1][0] = r2; b[nt * 2 + 1][1] = r3;                  \
            }                                                                  \
            _Pragma("unroll")                                                  \
            for (int mt = 0; mt < 4; mt++)                                     \
                _Pragma("unroll")                                              \
                for (int nt = 0; nt < 4; nt++)                                 \
                    mma16816(acc[mt][nt][0], acc[mt][nt][1],                   \
                             acc[mt][nt][2], acc[mt][nt][3],                   \
                             a[mt][0], a[mt][1], a[mt][2], a[mt][3],           \
                             b[nt][0], b[nt][1]);                              \
        }                                                                      \
        __syncthreads();                                                       \
    }

// ===========================================================================
// GEMM1: h = tanh(concept @ Wt^T + bt) -> bf16, + gate partial dots into graw.
// ===========================================================================
__global__ __launch_bounds__(256, 2) void gemm1_mma_kernel(
    const __nv_bfloat16* __restrict__ A,
    const __nv_bfloat16* __restrict__ B,
    const float* __restrict__ bias,
    __nv_bfloat16* __restrict__ Cb,
    const float* __restrict__ Wdiv,
    float* __restrict__ graw)
{
    extern __shared__ char smem[];
    const uint32_t sbase = smem_u32(smem);
    const int tid  = threadIdx.x;
    const int wid  = tid >> 5;
    const int lane = tid & 31;
    const int m0 = blockIdx.y * 128;
    const int n0 = blockIdx.x * 128;
    const int warp_m = wid & 1;
    const int warp_n = wid >> 1;

    GEMM_MAINLOOP(A, B, C_DIM)

    const int trow = lane >> 2;
    const int tcol = (lane & 3) * 2;
#pragma unroll
    for (int mt = 0; mt < 4; mt++) {
        const int gm = m0 + warp_m * 64 + mt * 16 + trow;
        float p0[3] = {0.f, 0.f, 0.f};
        float p1[3] = {0.f, 0.f, 0.f};
#pragma unroll
        for (int nt = 0; nt < 4; nt++) {
            int gn = n0 + warp_n * 32 + nt * 8 + tcol;
            float2 bv = *reinterpret_cast<const float2*>(bias + gn);
            float t0x = tanhf(acc[mt][nt][0] + bv.x);
            float t0y = tanhf(acc[mt][nt][1] + bv.y);
            float t1x = tanhf(acc[mt][nt][2] + bv.x);
            float t1y = tanhf(acc[mt][nt][3] + bv.y);
            *reinterpret_cast<__nv_bfloat162*>(Cb + (size_t)gm * C_DIM + gn) =
                __floats2bfloat162_rn(t0x, t0y);
            *reinterpret_cast<__nv_bfloat162*>(Cb + (size_t)(gm + 8) * C_DIM + gn) =
                __floats2bfloat162_rn(t1x, t1y);
#pragma unroll
            for (int j = 0; j < 3; j++) {
                float2 w = *reinterpret_cast<const float2*>(Wdiv + j * C_DIM + gn);
                p0[j] = fmaf(w.x, t0x, fmaf(w.y, t0y, p0[j]));
                p1[j] = fmaf(w.x, t1x, fmaf(w.y, t1y, p1[j]));
            }
        }
#pragma unroll
        for (int j = 0; j < 3; j++) {
            p0[j] += __shfl_xor_sync(0xffffffffu, p0[j], 1);
            p0[j] += __shfl_xor_sync(0xffffffffu, p0[j], 2);
            p1[j] += __shfl_xor_sync(0xffffffffu, p1[j], 1);
            p1[j] += __shfl_xor_sync(0xffffffffu, p1[j], 2);
        }
        if ((lane & 3) == 0) {
#pragma unroll
            for (int j = 0; j < 3; j++) {
                atomicAdd(&graw[gm * 3 + j], p0[j]);
                atomicAdd(&graw[(gm + 8) * 3 + j], p1[j]);
            }
        }
    }
}

// ===========================================================================
// GEMM2: 256x128 CTA tile, 512 thr (16 warps: 4m x 4n), BK=64, 3-stage.
// bf16 logits (coalesced via smem staging) + exp row sums.
// ===========================================================================
__global__ __launch_bounds__(512, 1) void gemm2_mma_kernel(
    const __nv_bfloat16* __restrict__ A,
    const __nv_bfloat16* __restrict__ B,
    const float* __restrict__ bias,
    __nv_bfloat16* __restrict__ Cb,
    float* __restrict__ rowsum)
{
    extern __shared__ char smem[];
    const uint32_t sbase = smem_u32(smem);
    const int tid  = threadIdx.x;
    const int wid  = tid >> 5;
    const int lane = tid & 31;
    const int m0 = blockIdx.y * 256;
    const int n0 = blockIdx.x * 128;
    const int warp_m = wid & 3;       // 0..3
    const int warp_n = wid >> 2;      // 0..3

    auto a_off = [&](int s) -> uint32_t { return sbase + s * G2_STAGE; };
    auto b_off = [&](int s) -> uint32_t { return sbase + s * G2_STAGE + G2_A_STAGE; };

    auto issue_stage = [&](int kt, int s) {
        const int k0 = kt * BK;
#pragma unroll
        for (int u = 0; u < 4; u++) {          // A: 2048 chunks / 512 thr
            int idx = tid + u * 512;
            int row = idx >> 3;
            int c   = idx & 7;
            cp16(a_off(s) + row * ROWB + c * 16,
                 A + (size_t)(m0 + row) * GK + k0 + c * 8, 16);
        }
#pragma unroll
        for (int u = 0; u < 2; u++) {          // B: 1024 chunks / 512 thr
            int idx = tid + u * 512;
            int row = idx >> 3;
            int c   = idx & 7;
            int gr = n0 + row;
            const void* ga = B + (size_t)(gr < V_DIM ? gr : V_DIM - 1) * GK + k0 + c * 8;
            cp16(b_off(s) + row * ROWB + c * 16, ga, (gr < V_DIM) ? 16u : 0u);
        }
        cp_commit();
    };

    float acc[4][4][4];
#pragma unroll
    for (int i = 0; i < 4; i++)
#pragma unroll
        for (int j = 0; j < 4; j++)
#pragma unroll
            for (int e = 0; e < 4; e++) acc[i][j][e] = 0.f;

    issue_stage(0, 0);
    issue_stage(1, 1);

    const int g    = lane >> 3;
    const int lrow = lane & 7;

#pragma unroll
    for (int kt = 0; kt < NKT; kt++) {
        const int s = kt % NSTAGE;
        if (kt + 2 < NKT) {
            issue_stage(kt + 2, (kt + 2) % NSTAGE);
            cp_wait<2>();
        } else if (kt + 1 < NKT) {
            cp_wait<1>();
        } else {
            cp_wait<0>();
        }
        __syncthreads();

        const uint32_t abase = a_off(s);
        const uint32_t bbase = b_off(s);

#pragma unroll
        for (int ks = 0; ks < 4; ks++) {
            uint32_t a[4][4];
#pragma unroll
            for (int mt = 0; mt < 4; mt++) {
                int row = warp_m * 64 + mt * 16 + lrow + (g & 1) * 8;
                int chunk = ks * 2 + (g >> 1);
                ldmx4(abase + row * ROWB + chunk * 16,
                      a[mt][0], a[mt][1], a[mt][2], a[mt][3]);
            }
            uint32_t b[4][2];
#pragma unroll
            for (int nt = 0; nt < 2; nt++) {
                int row = warp_n * 32 + nt * 16 + lrow + (g >> 1) * 8;
                int chunk = ks * 2 + (g & 1);
                uint32_t r0, r1, r2, r3;
                ldmx4(bbase + row * ROWB + chunk * 16, r0, r1, r2, r3);
                b[nt * 2 + 0][0] = r0; b[nt * 2 + 0][1] = r1;
                b[nt * 2 + 1][0] = r2; b[nt * 2 + 1][1] = r3;
            }
#pragma unroll
            for (int mt = 0; mt < 4; mt++)
#pragma unroll
                for (int nt = 0; nt < 4; nt++)
                    mma16816(acc[mt][nt][0], acc[mt][nt][1],
                             acc[mt][nt][2], acc[mt][nt][3],
                             a[mt][0], a[mt][1], a[mt][2], a[mt][3],
                             b[nt][0], b[nt][1]);
        }
        __syncthreads();
    }

    // ---- epilogue: exp rowsums + stage bf16 tile (256 x 128) in smem ----
    const int trow = lane >> 2;
    const int tcol = (lane & 3) * 2;
#pragma unroll
    for (int mt = 0; mt < 4; mt++) {
        const int gm = m0 + warp_m * 64 + mt * 16 + trow;
        const int srow = warp_m * 64 + mt * 16 + trow;
        float rs0 = 0.f, rs1 = 0.f;
#pragma unroll
        for (int nt = 0; nt < 4; nt++) {
            int gn = n0 + warp_n * 32 + nt * 8 + tcol;
            int scol = warp_n * 32 + nt * 8 + tcol;
            float l0 = 0.f, l1 = 0.f, l2 = 0.f, l3 = 0.f;
            if (gn < V_DIM) {
                float2 bv = *reinterpret_cast<const float2*>(bias + gn);
                l0 = acc[mt][nt][0] + bv.x;
                l1 = acc[mt][nt][1] + bv.y;
                l2 = acc[mt][nt][2] + bv.x;
                l3 = acc[mt][nt][3] + bv.y;
                rs0 += __expf(l0) + __expf(l1);
                rs1 += __expf(l2) + __expf(l3);
            }
            *reinterpret_cast<__nv_bfloat162*>(smem + srow * ROWB_STG + scol * 2) =
                __floats2bfloat162_rn(l0, l1);
            *reinterpret_cast<__nv_bfloat162*>(smem + (srow + 8) * ROWB_STG + scol * 2) =
                __floats2bfloat162_rn(l2, l3);
        }
        rs0 += __shfl_xor_sync(0xffffffffu, rs0, 1);
        rs0 += __shfl_xor_sync(0xffffffffu, rs0, 2);
        rs1 += __shfl_xor_sync(0xffffffffu, rs1, 1);
        rs1 += __shfl_xor_sync(0xffffffffu, rs1, 2);
        if ((lane & 3) == 0) {
            atomicAdd(&rowsum[gm], rs0);
            atomicAdd(&rowsum[gm + 8], rs1);
        }
    }
    __syncthreads();

    // ---- coalesced bf16 writes: 256 rows x 16 chunks / 512 thr = 8 per thr ----
#pragma unroll
    for (int u = 0; u < 8; u++) {
        int idx = tid + u * 512;
        int row = idx >> 4;
        int chunk = idx & 15;
        int gn0 = n0 + chunk * 8;
        if (gn0 < V_DIM) {
            uint4 v = *reinterpret_cast<const uint4*>(smem + row * ROWB_STG + chunk * 16);
            *reinterpret_cast<uint4*>(Cb + (size_t)(m0 + row) * V_DIM + gn0) = v;
        }
    }
}

// ===========================================================================
// fused fp32 -> bf16 conversion (concept, Wt, Wg in one launch)
// ===========================================================================
__global__ __launch_bounds__(256) void convert_all_kernel(
    const float4* __restrict__ c,  uint2* __restrict__ co, int n1,
    const float4* __restrict__ wt, uint2* __restrict__ wo, int n2,
    const float4* __restrict__ wg, uint2* __restrict__ go, int n3)
{
    int i = blockIdx.x * blockDim.x + threadIdx.x;
    const float4* src;
    uint2* dst;
    int j = i;
    if (j < n1) { src = c; dst = co; }
    else {
        j -= n1;
        if (j < n2) { src = wt; dst = wo; }
        else {
            j -= n2;
            if (j >= n3) return;
            src = wg; dst = go;
        }
    }
    float4 v = src[j];
    __nv_bfloat162 lo = __floats2bfloat162_rn(v.x, v.y);
    __nv_bfloat162 hi = __floats2bfloat162_rn(v.z, v.w);
    uint2 o;
    o.x = *reinterpret_cast<uint32_t*>(&lo);
    o.y = *reinterpret_cast<uint32_t*>(&hi);
    dst[j] = o;
}

// ===========================================================================
// finalize (single pass): gates softmax3 inline; scale = gen/rowsum;
// K = log(scale). non-scattered: ll = logit + K; scattered: fast-math log.
// ===========================================================================
__global__ __launch_bounds__(512) void finalize_kernel(
    float* __restrict__ out,
    const __nv_bfloat16* __restrict__ Lb,   // (M_ROWS, V_DIM) bf16 logits
    const float* __restrict__ align,        // (SRC, B, SNT)
    const int*   __restrict__ copy_seq,     // (SNT, B, 2)
    const float* __restrict__ bdiv)
{
    extern __shared__ __align__(16) float scat[];   // TOT_DIM floats

    const int r = blockIdx.x;
    const int b = r & (BSZ - 1);
    const int tid = threadIdx.x;
    float4* out4 = reinterpret_cast<float4*>(out + (size_t)r * TOT_DIM);
    const uint4* lrow = reinterpret_cast<const uint4*>(Lb + (size_t)r * V_DIM);
    float4* scat4 = reinterpret_cast<float4*>(scat);

    // gates softmax3 (redundant per thread, trivial)
    float s0 = g_graw[r * 3 + 0] + bdiv[0];
    float s1 = g_graw[r * 3 + 1] + bdiv[1];
    float s2 = g_graw[r * 3 + 2] + bdiv[2];
    float mx = fmaxf(s0, fmaxf(s1, s2));
    float e0 = __expf(s0 - mx), e1 = __expf(s1 - mx), e2 = __expf(s2 - mx);
    float inv = 1.f / (e0 + e1 + e2);
    const float gen = e0 * inv;
    const float mp  = e1 * inv;   // map gate (gates[...,1])
    const float cpy = e2 * inv;   // copy gate (gates[...,2])
    const float scale = gen / g_rowsum[r];
    const float K = logf(scale);

    // zero scatter buffer
    for (int c = tid; c < T4; c += 512)
        scat4[c] = make_float4(0.f, 0.f, 0.f, 0.f);
    __syncthreads();

    // scatter-add 1024 copy probabilities into smem
    const float* arow = align + (size_t)r * SNT_LEN;
    for (int j = tid; j < 2 * SNT_LEN; j += 512) {
        int snt = j >> 1;
        int k = j & 1;
        int idx = copy_seq[((size_t)snt * BSZ + b) * 2 + k];
        float v = (k == 0 ? cpy : mp) * arow[snt];
        if (idx >= 0 && idx < TOT_DIM) atomicAdd(&scat[idx], v);
    }
    __syncthreads();

    // vocab region: 8 bf16 logits per uint4 (fast-math predicated paths)
    for (int c = tid; c < V8; c += 512) {
        uint4 p = lrow[c];
        float l[8];
        {
            const uint32_t* w = &p.x;
#pragma unroll
            for (int i = 0; i < 4; i++) {
                float2 f = __bfloat1622float2(
                    *reinterpret_cast<const __nv_bfloat162*>(&w[i]));
                l[i * 2] = f.x; l[i * 2 + 1] = f.y;
            }
        }
        float4 sc0 = scat4[2 * c];
        float4 sc1 = scat4[2 * c + 1];
        float4 o0, o1;
        o0.x = (sc0.x > 0.f) ? __logf(__expf(l[0]) * scale + sc0.x + 1e-12f) : l[0] + K;
        o0.y = (sc0.y > 0.f) ? __logf(__expf(l[1]) * scale + sc0.y + 1e-12f) : l[1] + K;
        o0.z = (sc0.z > 0.f) ? __logf(__expf(l[2]) * scale + sc0.z + 1e-12f) : l[2] + K;
        o0.w = (sc0.w > 0.f) ? __logf(__expf(l[3]) * scale + sc0.w + 1e-12f) : l[3] + K;
        o1.x = (sc1.x > 0.f) ? __logf(__expf(l[4]) * scale + sc1.x + 1e-12f) : l[4] + K;
        o1.y = (sc1.y > 0.f) ? __logf(__expf(l[5]) * scale + sc1.y + 1e-12f) : l[5] + K;
        o1.z = (sc1.z > 0.f) ? __logf(__expf(l[6]) * scale + sc1.z + 1e-12f) : l[6] + K;
        o1.w = (sc1.w > 0.f) ? __logf(__expf(l[7]) * scale + sc1.w + 1e-12f) : l[7] + K;
        out4[2 * c] = o0;
        out4[2 * c + 1] = o1;
    }
    // ext region
    for (int c = V4 + tid; c < T4; c += 512) {
        float4 sc = scat4[c];
        float4 o;
        o.x = (sc.x > 0.f) ? __logf(sc.x + 1e-12f) : LOG_EPS;
        o.y = (sc.y > 0.f) ? __logf(sc.y + 1e-12f) : LOG_EPS;
        o.z = (sc.z > 0.f) ? __logf(sc.z + 1e-12f) : LOG_EPS;
        o.w = (sc.w > 0.f) ? __logf(sc.w + 1e-12f) : LOG_EPS;
        out4[c] = o;
    }
}

// ===========================================================================
// arc_ll = log(arc + 1e-12)
// ===========================================================================
__global__ __launch_bounds__(256) void arc_log_kernel(
    const float4* __restrict__ in, float4* __restrict__ out, int n4)
{
    int i = blockIdx.x * blockDim.x + threadIdx.x;
    if (i < n4) {
        float4 v = in[i];
        v.x = logf(v.x + 1e-12f);
        v.y = logf(v.y + 1e-12f);
        v.z = logf(v.z + 1e-12f);
        v.w = logf(v.w + 1e-12f);
        out[i] = v;
    }
}

// ===========================================================================
extern "C" void kernel_launch(void* const* d_in, const int* in_sizes, int n_in,
                              void* d_out, int out_size)
{
    const float* align    = (const float*)d_in[0];
    const float* arc      = (const float*)d_in[1];
    const float* concept  = (const float*)d_in[3];
    const int*   copy_seq = (const int*)  d_in[4];
    const float* Wt       = (const float*)d_in[9];
    const float* bt       = (const float*)d_in[10];
    const float* Wg       = (const float*)d_in[11];
    const float* bg       = (const float*)d_in[12];
    const float* Wd       = (const float*)d_in[13];
    const float* bd       = (const float*)d_in[14];

    float* out = (float*)d_out;
    float* ll = out;                         // (SRC,B,TOT)
    float* arc_ll = out + LL_ELEMS;          // (SRC,B,SRC)

    __nv_bfloat16 *cbf = nullptr, *wtbf = nullptr, *hbf = nullptr,
                  *wgbf = nullptr, *lbf = nullptr;
    float *rowsum = nullptr, *graw = nullptr;
    cudaGetSymbolAddress((void**)&cbf,  g_concept_bf);
    cudaGetSymbolAddress((void**)&wtbf, g_Wt_bf);
    cudaGetSymbolAddress((void**)&hbf,  g_h_bf);
    cudaGetSymbolAddress((void**)&wgbf, g_Wg_bf);
    cudaGetSymbolAddress((void**)&lbf,  g_logit_bf);
    cudaGetSymbolAddress((void**)&rowsum, g_rowsum);
    cudaGetSymbolAddress((void**)&graw, g_graw);

    cudaFuncSetAttribute(gemm1_mma_kernel,
                         cudaFuncAttributeMaxDynamicSharedMemorySize, GEMM_SMEM);
    cudaFuncSetAttribute(gemm2_mma_kernel,
                         cudaFuncAttributeMaxDynamicSharedMemorySize, G2_SMEM);

    // 0) zero accumulators + fused conversions to bf16
    cudaMemsetAsync(rowsum, 0, M_ROWS * sizeof(float));
    cudaMemsetAsync(graw, 0, M_ROWS * 3 * sizeof(float));
    {
        int n1 = M_ROWS * E_DIM / 4;
        int n2 = C_DIM * E_DIM / 4;
        int n3 = V_DIM * C_DIM / 4;
        int ntot = n1 + n2 + n3;
        convert_all_kernel<<<(ntot + 255) / 256, 256>>>(
            (const float4*)concept, (uint2*)cbf, n1,
            (const float4*)Wt, (uint2*)wtbf, n2,
            (const float4*)Wg, (uint2*)wgbf, n3);
    }

    // 1) h = tanh(concept @ Wt^T + bt) -> bf16, + gate partials
    {
        dim3 grid(C_DIM / 128, M_ROWS / 128);
        gemm1_mma_kernel<<<grid, 256, GEMM_SMEM>>>(cbf, wtbf, bt, hbf, Wd, graw);
    }

    // 2) logits (bf16, coalesced) + exp row sums — 256x128 tiles
    {
        dim3 grid((V_DIM + 127) / 128, M_ROWS / 256);
        gemm2_mma_kernel<<<grid, 512, G2_SMEM>>>(hbf, wgbf, bg, lbf, rowsum);
    }

    // 3) finalize: single pass, gates inline, fast-math predicated paths
    {
        int smem = TOT_DIM * sizeof(float);  // 50000 B
        cudaFuncSetAttribute(finalize_kernel,
                             cudaFuncAttributeMaxDynamicSharedMemorySize, smem);
        finalize_kernel<<<M_ROWS, 512, smem>>>(ll, lbf, align, copy_seq, bd);
    }

    // 4) arc_ll
    {
        int n4 = (SRC_LEN * BSZ * SRC_LEN) / 4;
        arc_log_kernel<<<(n4 + 255) / 256, 256>>>((const float4*)arc,
                                                  (float4*)arc_ll, n4);
    }
}

// round 16
// speedup vs baseline: 1.0586x; 1.0586x over previous
#include <cuda_runtime.h>
#include <cuda_bf16.h>
#include <math.h>
#include <stdint.h>

// Problem constants (fixed shapes)
#define SRC_LEN 512
#define BSZ     16
#define SNT_LEN 512
#define E_DIM   512
#define C_DIM   512
#define V_DIM   12000
#define EXT_DIM 500
#define TOT_DIM (V_DIM + EXT_DIM)       // 12500
#define M_ROWS  (SRC_LEN * BSZ)         // 8192
#define LL_ELEMS ((size_t)M_ROWS * TOT_DIM)
#define LOG_EPS (-27.6310211159f)       // log(1e-12)

// Scratch (device globals — no allocations allowed)
__device__ __nv_bfloat16 g_concept_bf[(size_t)M_ROWS * E_DIM];
__device__ __nv_bfloat16 g_Wt_bf[(size_t)C_DIM * E_DIM];
__device__ __nv_bfloat16 g_h_bf[(size_t)M_ROWS * C_DIM];
__device__ __nv_bfloat16 g_Wg_bf[(size_t)V_DIM * C_DIM];
__device__ __nv_bfloat16 g_logit_bf[(size_t)M_ROWS * V_DIM];  // bf16 logits
__device__ float g_graw[M_ROWS * 3];    // raw gate logits (pre-softmax, no bias)
__device__ float g_rowsum[M_ROWS];      // sum of exp(logits) per row

#define GK   512
#define BK   64
#define NKT  (GK / BK)            // 8
#define ROWB 144                  // padded smem row stride (bytes)
#define STAGE_BYTES (128 * ROWB)  // 18432 per operand per stage
#define NSTAGE 3
#define GEMM_SMEM (NSTAGE * 2 * STAGE_BYTES)   // 110592
#define ROWB_STG 272              // epilogue staging stride (17*16)

#define V4   (V_DIM / 4)      // 3000
#define T4   (TOT_DIM / 4)    // 3125
#define V8   (V_DIM / 8)      // 1500
#define FTHREADS 1024

__device__ __forceinline__ uint32_t smem_u32(const void* p) {
    uint32_t a;
    asm("{ .reg .u64 t; cvta.to.shared.u64 t, %1; cvt.u32.u64 %0, t; }"
        : "=r"(a) : "l"(p));
    return a;
}
__device__ __forceinline__ void cp16(uint32_t saddr, const void* gaddr, uint32_t srcsz) {
    asm volatile("cp.async.cg.shared.global [%0], [%1], 16, %2;"
                 :: "r"(saddr), "l"(gaddr), "r"(srcsz));
}
__device__ __forceinline__ void cp_commit() {
    asm volatile("cp.async.commit_group;");
}
template <int N>
__device__ __forceinline__ void cp_wait() {
    asm volatile("cp.async.wait_group %0;" :: "n"(N));
}
__device__ __forceinline__ void ldmx4(uint32_t addr, uint32_t& r0, uint32_t& r1,
                                      uint32_t& r2, uint32_t& r3) {
    asm volatile("ldmatrix.sync.aligned.m8n8.x4.shared.b16 {%0,%1,%2,%3}, [%4];"
                 : "=r"(r0), "=r"(r1), "=r"(r2), "=r"(r3) : "r"(addr));
}
__device__ __forceinline__ void mma16816(float& c0, float& c1, float& c2, float& c3,
                                         uint32_t a0, uint32_t a1, uint32_t a2, uint32_t a3,
                                         uint32_t b0, uint32_t b1) {
    asm volatile(
        "mma.sync.aligned.m16n8k16.row.col.f32.bf16.bf16.f32 "
        "{%0,%1,%2,%3}, {%4,%5,%6,%7}, {%8,%9}, {%0,%1,%2,%3};"
        : "+f"(c0), "+f"(c1), "+f"(c2), "+f"(c3)
        : "r"(a0), "r"(a1), "r"(a2), "r"(a3), "r"(b0), "r"(b1));
}
__device__ __forceinline__ void stcs128(float4* p, float4 v) {
    asm volatile("st.global.cs.v4.f32 [%0], {%1,%2,%3,%4};"
                 :: "l"(p), "f"(v.x), "f"(v.y), "f"(v.z), "f"(v.w) : "memory");
}

// ===========================================================================
// shared mainloop body (128x128, 256 thr)
// ===========================================================================
#define GEMM_MAINLOOP(A_, B_, NGUARD)                                          \
    auto a_off = [&](int s) -> uint32_t { return sbase + s * 2 * STAGE_BYTES; };\
    auto b_off = [&](int s) -> uint32_t { return sbase + s * 2 * STAGE_BYTES + STAGE_BYTES; };\
    auto issue_stage = [&](int kt, int s) {                                    \
        const int k0 = kt * BK;                                                \
        _Pragma("unroll")                                                      \
        for (int u = 0; u < 4; u++) {                                          \
            int idx = tid + u * 256;                                           \
            int row = idx >> 3;                                                \
            int c   = idx & 7;                                                 \
            cp16(a_off(s) + row * ROWB + c * 16,                               \
                 A_ + (size_t)(m0 + row) * GK + k0 + c * 8, 16);               \
        }                                                                      \
        _Pragma("unroll")                                                      \
        for (int u = 0; u < 4; u++) {                                          \
            int idx = tid + u * 256;                                           \
            int row = idx >> 3;                                                \
            int c   = idx & 7;                                                 \
            int gr = n0 + row;                                                 \
            const void* ga = B_ + (size_t)(gr < NGUARD ? gr : NGUARD - 1) * GK + k0 + c * 8;\
            cp16(b_off(s) + row * ROWB + c * 16, ga, (gr < NGUARD) ? 16u : 0u);\
        }                                                                      \
        cp_commit();                                                           \
    };                                                                         \
    float acc[4][4][4];                                                        \
    _Pragma("unroll")                                                          \
    for (int i = 0; i < 4; i++)                                                \
        _Pragma("unroll")                                                      \
        for (int j = 0; j < 4; j++)                                            \
            _Pragma("unroll")                                                  \
            for (int e = 0; e < 4; e++) acc[i][j][e] = 0.f;                    \
    issue_stage(0, 0);                                                         \
    issue_stage(1, 1);                                                         \
    const int g    = lane >> 3;                                                \
    const int lrow = lane & 7;                                                 \
    _Pragma("unroll")                                                          \
    for (int kt = 0; kt < NKT; kt++) {                                         \
        const int s = kt % NSTAGE;                                             \
        if (kt + 2 < NKT) {                                                    \
            issue_stage(kt + 2, (kt + 2) % NSTAGE);                            \
            cp_wait<2>();                                                      \
        } else if (kt + 1 < NKT) {                                             \
            cp_wait<1>();                                                      \
        } else {                                                               \
            cp_wait<0>();                                                      \
        }                                                                      \
        __syncthreads();                                                       \
        const uint32_t abase = a_off(s);                                       \
        const uint32_t bbase = b_off(s);                                       \
        _Pragma("unroll")                                                      \
        for (int ks = 0; ks < 4; ks++) {                                       \
            uint32_t a[4][4];                                                  \
            _Pragma("unroll")                                                  \
            for (int mt = 0; mt < 4; mt++) {                                   \
                int row = warp_m * 64 + mt * 16 + lrow + (g & 1) * 8;          \
                int chunk = ks * 2 + (g >> 1);                                 \
                ldmx4(abase + row * ROWB + chunk * 16,                         \
                      a[mt][0], a[mt][1], a[mt][2], a[mt][3]);                 \
            }                                                                  \
            uint32_t b[4][2];                                                  \
            _Pragma("unroll")                                                  \
            for (int nt = 0; nt < 2; nt++) {                                   \
                int row = warp_n * 32 + nt * 16 + lrow + (g >> 1) * 8;         \
                int chunk = ks * 2 + (g & 1);                                  \
                uint32_t r0, r1, r2, r3;                                       \
                ldmx4(bbase + row * ROWB + chunk * 16, r0, r1, r2, r3);        \
                b[nt * 2 + 0][0] = r0; b[nt * 2 + 0][1] = r1;                  \
                b[nt * 2 + 1][0] = r2; b[nt * 2 + 1][1] = r3;                  \
            }                                                                  \
            _Pragma("unroll")                                                  \
            for (int mt = 0; mt < 4; mt++)                                     \
                _Pragma("unroll")                                              \
                for (int nt = 0; nt < 4; nt++)                                 \
                    mma16816(acc[mt][nt][0], acc[mt][nt][1],                   \
                             acc[mt][nt][2], acc[mt][nt][3],                   \
                             a[mt][0], a[mt][1], a[mt][2], a[mt][3],           \
                             b[nt][0], b[nt][1]);                              \
        }                                                                      \
        __syncthreads();                                                       \
    }

// ===========================================================================
// GEMM1: h = tanh(concept @ Wt^T + bt) -> bf16, + gate partial dots into graw.
// ===========================================================================
__global__ __launch_bounds__(256, 2) void gemm1_mma_kernel(
    const __nv_bfloat16* __restrict__ A,
    const __nv_bfloat16* __restrict__ B,
    const float* __restrict__ bias,
    __nv_bfloat16* __restrict__ Cb,
    const float* __restrict__ Wdiv,
    float* __restrict__ graw)
{
    extern __shared__ char smem[];
    const uint32_t sbase = smem_u32(smem);
    const int tid  = threadIdx.x;
    const int wid  = tid >> 5;
    const int lane = tid & 31;
    const int m0 = blockIdx.y * 128;
    const int n0 = blockIdx.x * 128;
    const int warp_m = wid & 1;
    const int warp_n = wid >> 1;

    GEMM_MAINLOOP(A, B, C_DIM)

    const int trow = lane >> 2;
    const int tcol = (lane & 3) * 2;
#pragma unroll
    for (int mt = 0; mt < 4; mt++) {
        const int gm = m0 + warp_m * 64 + mt * 16 + trow;
        float p0[3] = {0.f, 0.f, 0.f};
        float p1[3] = {0.f, 0.f, 0.f};
#pragma unroll
        for (int nt = 0; nt < 4; nt++) {
            int gn = n0 + warp_n * 32 + nt * 8 + tcol;
            float2 bv = *reinterpret_cast<const float2*>(bias + gn);
            float t0x = tanhf(acc[mt][nt][0] + bv.x);
            float t0y = tanhf(acc[mt][nt][1] + bv.y);
            float t1x = tanhf(acc[mt][nt][2] + bv.x);
            float t1y = tanhf(acc[mt][nt][3] + bv.y);
            *reinterpret_cast<__nv_bfloat162*>(Cb + (size_t)gm * C_DIM + gn) =
                __floats2bfloat162_rn(t0x, t0y);
            *reinterpret_cast<__nv_bfloat162*>(Cb + (size_t)(gm + 8) * C_DIM + gn) =
                __floats2bfloat162_rn(t1x, t1y);
#pragma unroll
            for (int j = 0; j < 3; j++) {
                float2 w = *reinterpret_cast<const float2*>(Wdiv + j * C_DIM + gn);
                p0[j] = fmaf(w.x, t0x, fmaf(w.y, t0y, p0[j]));
                p1[j] = fmaf(w.x, t1x, fmaf(w.y, t1y, p1[j]));
            }
        }
#pragma unroll
        for (int j = 0; j < 3; j++) {
            p0[j] += __shfl_xor_sync(0xffffffffu, p0[j], 1);
            p0[j] += __shfl_xor_sync(0xffffffffu, p0[j], 2);
            p1[j] += __shfl_xor_sync(0xffffffffu, p1[j], 1);
            p1[j] += __shfl_xor_sync(0xffffffffu, p1[j], 2);
        }
        if ((lane & 3) == 0) {
#pragma unroll
            for (int j = 0; j < 3; j++) {
                atomicAdd(&graw[gm * 3 + j], p0[j]);
                atomicAdd(&graw[(gm + 8) * 3 + j], p1[j]);
            }
        }
    }
}

// ===========================================================================
// GEMM2: bf16 logits (coalesced via smem staging) + exp row sums. (R14 cfg)
// ===========================================================================
__global__ __launch_bounds__(256, 2) void gemm2_mma_kernel(
    const __nv_bfloat16* __restrict__ A,
    const __nv_bfloat16* __restrict__ B,
    const float* __restrict__ bias,
    __nv_bfloat16* __restrict__ Cb,
    float* __restrict__ rowsum)
{
    extern __shared__ char smem[];
    const uint32_t sbase = smem_u32(smem);
    const int tid  = threadIdx.x;
    const int wid  = tid >> 5;
    const int lane = tid & 31;
    const int m0 = blockIdx.y * 128;
    const int n0 = blockIdx.x * 128;
    const int warp_m = wid & 1;
    const int warp_n = wid >> 1;

    GEMM_MAINLOOP(A, B, V_DIM)

    // ---- epilogue: exp rowsums + stage bf16 tile in smem ----
    const int trow = lane >> 2;
    const int tcol = (lane & 3) * 2;
#pragma unroll
    for (int mt = 0; mt < 4; mt++) {
        const int gm = m0 + warp_m * 64 + mt * 16 + trow;
        const int srow = warp_m * 64 + mt * 16 + trow;
        float rs0 = 0.f, rs1 = 0.f;
#pragma unroll
        for (int nt = 0; nt < 4; nt++) {
            int gn = n0 + warp_n * 32 + nt * 8 + tcol;
            int scol = warp_n * 32 + nt * 8 + tcol;
            float l0 = 0.f, l1 = 0.f, l2 = 0.f, l3 = 0.f;
            if (gn < V_DIM) {
                float2 bv = *reinterpret_cast<const float2*>(bias + gn);
                l0 = acc[mt][nt][0] + bv.x;
                l1 = acc[mt][nt][1] + bv.y;
                l2 = acc[mt][nt][2] + bv.x;
                l3 = acc[mt][nt][3] + bv.y;
                rs0 += __expf(l0) + __expf(l1);
                rs1 += __expf(l2) + __expf(l3);
            }
            *reinterpret_cast<__nv_bfloat162*>(smem + srow * ROWB_STG + scol * 2) =
                __floats2bfloat162_rn(l0, l1);
            *reinterpret_cast<__nv_bfloat162*>(smem + (srow + 8) * ROWB_STG + scol * 2) =
                __floats2bfloat162_rn(l2, l3);
        }
        rs0 += __shfl_xor_sync(0xffffffffu, rs0, 1);
        rs0 += __shfl_xor_sync(0xffffffffu, rs0, 2);
        rs1 += __shfl_xor_sync(0xffffffffu, rs1, 1);
        rs1 += __shfl_xor_sync(0xffffffffu, rs1, 2);
        if ((lane & 3) == 0) {
            atomicAdd(&rowsum[gm], rs0);
            atomicAdd(&rowsum[gm + 8], rs1);
        }
    }
    __syncthreads();

    // ---- coalesced bf16 writes: 16B per thread, contiguous runs ----
#pragma unroll
    for (int u = 0; u < 8; u++) {
        int idx = tid + u * 256;
        int row = idx >> 4;
        int chunk = idx & 15;
        int gn0 = n0 + chunk * 8;
        if (gn0 < V_DIM) {
            uint4 v = *reinterpret_cast<const uint4*>(smem + row * ROWB_STG + chunk * 16);
            *reinterpret_cast<uint4*>(Cb + (size_t)(m0 + row) * V_DIM + gn0) = v;
        }
    }
}

// ===========================================================================
// fused fp32 -> bf16 conversion (concept, Wt, Wg in one launch)
// ===========================================================================
__global__ __launch_bounds__(256) void convert_all_kernel(
    const float4* __restrict__ c,  uint2* __restrict__ co, int n1,
    const float4* __restrict__ wt, uint2* __restrict__ wo, int n2,
    const float4* __restrict__ wg, uint2* __restrict__ go, int n3)
{
    int i = blockIdx.x * blockDim.x + threadIdx.x;
    const float4* src;
    uint2* dst;
    int j = i;
    if (j < n1) { src = c; dst = co; }
    else {
        j -= n1;
        if (j < n2) { src = wt; dst = wo; }
        else {
            j -= n2;
            if (j >= n3) return;
            src = wg; dst = go;
        }
    }
    float4 v = src[j];
    __nv_bfloat162 lo = __floats2bfloat162_rn(v.x, v.y);
    __nv_bfloat162 hi = __floats2bfloat162_rn(v.z, v.w);
    uint2 o;
    o.x = *reinterpret_cast<uint32_t*>(&lo);
    o.y = *reinterpret_cast<uint32_t*>(&hi);
    dst[j] = o;
}

// ===========================================================================
// finalize (single pass, 1024 thr): gates softmax3 inline; scale=gen/rowsum;
// K = log(scale). non-scattered: ll = logit + K; scattered: fast-math log.
// Streaming (cs) stores for the 410 MB output.
// ===========================================================================
__global__ __launch_bounds__(FTHREADS) void finalize_kernel(
    float* __restrict__ out,
    const __nv_bfloat16* __restrict__ Lb,   // (M_ROWS, V_DIM) bf16 logits
    const float* __restrict__ align,        // (SRC, B, SNT)
    const int*   __restrict__ copy_seq,     // (SNT, B, 2)
    const float* __restrict__ bdiv)
{
    extern __shared__ __align__(16) float scat[];   // TOT_DIM floats

    const int r = blockIdx.x;
    const int b = r & (BSZ - 1);
    const int tid = threadIdx.x;
    float4* out4 = reinterpret_cast<float4*>(out + (size_t)r * TOT_DIM);
    const uint4* lrow = reinterpret_cast<const uint4*>(Lb + (size_t)r * V_DIM);
    float4* scat4 = reinterpret_cast<float4*>(scat);

    // gates softmax3 (redundant per thread, trivial)
    float s0 = g_graw[r * 3 + 0] + bdiv[0];
    float s1 = g_graw[r * 3 + 1] + bdiv[1];
    float s2 = g_graw[r * 3 + 2] + bdiv[2];
    float mx = fmaxf(s0, fmaxf(s1, s2));
    float e0 = __expf(s0 - mx), e1 = __expf(s1 - mx), e2 = __expf(s2 - mx);
    float inv = 1.f / (e0 + e1 + e2);
    const float gen = e0 * inv;
    const float mp  = e1 * inv;   // map gate (gates[...,1])
    const float cpy = e2 * inv;   // copy gate (gates[...,2])
    const float scale = gen / g_rowsum[r];
    const float K = logf(scale);

    // zero scatter buffer
    for (int c = tid; c < T4; c += FTHREADS)
        scat4[c] = make_float4(0.f, 0.f, 0.f, 0.f);
    __syncthreads();

    // scatter-add 1024 copy probabilities into smem (one per thread)
    const float* arow = align + (size_t)r * SNT_LEN;
    {
        int j = tid;   // FTHREADS == 2*SNT_LEN
        int snt = j >> 1;
        int k = j & 1;
        int idx = copy_seq[((size_t)snt * BSZ + b) * 2 + k];
        float v = (k == 0 ? cpy : mp) * arow[snt];
        if (idx >= 0 && idx < TOT_DIM) atomicAdd(&scat[idx], v);
    }
    __syncthreads();

    // vocab region: 8 bf16 logits per uint4 (fast-math predicated paths)
    for (int c = tid; c < V8; c += FTHREADS) {
        uint4 p = lrow[c];
        float l[8];
        {
            const uint32_t* w = &p.x;
#pragma unroll
            for (int i = 0; i < 4; i++) {
                float2 f = __bfloat1622float2(
                    *reinterpret_cast<const __nv_bfloat162*>(&w[i]));
                l[i * 2] = f.x; l[i * 2 + 1] = f.y;
            }
        }
        float4 sc0 = scat4[2 * c];
        float4 sc1 = scat4[2 * c + 1];
        float4 o0, o1;
        o0.x = (sc0.x > 0.f) ? __logf(__expf(l[0]) * scale + sc0.x + 1e-12f) : l[0] + K;
        o0.y = (sc0.y > 0.f) ? __logf(__expf(l[1]) * scale + sc0.y + 1e-12f) : l[1] + K;
        o0.z = (sc0.z > 0.f) ? __logf(__expf(l[2]) * scale + sc0.z + 1e-12f) : l[2] + K;
        o0.w = (sc0.w > 0.f) ? __logf(__expf(l[3]) * scale + sc0.w + 1e-12f) : l[3] + K;
        o1.x = (sc1.x > 0.f) ? __logf(__expf(l[4]) * scale + sc1.x + 1e-12f) : l[4] + K;
        o1.y = (sc1.y > 0.f) ? __logf(__expf(l[5]) * scale + sc1.y + 1e-12f) : l[5] + K;
        o1.z = (sc1.z > 0.f) ? __logf(__expf(l[6]) * scale + sc1.z + 1e-12f) : l[6] + K;
        o1.w = (sc1.w > 0.f) ? __logf(__expf(l[7]) * scale + sc1.w + 1e-12f) : l[7] + K;
        stcs128(&out4[2 * c], o0);
        stcs128(&out4[2 * c + 1], o1);
    }
    // ext region
    for (int c = V4 + tid; c < T4; c += FTHREADS) {
        float4 sc = scat4[c];
        float4 o;
        o.x = (sc.x > 0.f) ? __logf(sc.x + 1e-12f) : LOG_EPS;
        o.y = (sc.y > 0.f) ? __logf(sc.y + 1e-12f) : LOG_EPS;
        o.z = (sc.z > 0.f) ? __logf(sc.z + 1e-12f) : LOG_EPS;
        o.w = (sc.w > 0.f) ? __logf(sc.w + 1e-12f) : LOG_EPS;
        stcs128(&out4[c], o);
    }
}

// ===========================================================================
// arc_ll = log(arc + 1e-12)
// ===========================================================================
__global__ __launch_bounds__(256) void arc_log_kernel(
    const float4* __restrict__ in, float4* __restrict__ out, int n4)
{
    int i = blockIdx.x * blockDim.x + threadIdx.x;
    if (i < n4) {
        float4 v = in[i];
        v.x = logf(v.x + 1e-12f);
        v.y = logf(v.y + 1e-12f);
        v.z = logf(v.z + 1e-12f);
        v.w = logf(v.w + 1e-12f);
        out[i] = v;
    }
}

// ===========================================================================
extern "C" void kernel_launch(void* const* d_in, const int* in_sizes, int n_in,
                              void* d_out, int out_size)
{
    const float* align    = (const float*)d_in[0];
    const float* arc      = (const float*)d_in[1];
    const float* concept  = (const float*)d_in[3];
    const int*   copy_seq = (const int*)  d_in[4];
    const float* Wt       = (const float*)d_in[9];
    const float* bt       = (const float*)d_in[10];
    const float* Wg       = (const float*)d_in[11];
    const float* bg       = (const float*)d_in[12];
    const float* Wd       = (const float*)d_in[13];
    const float* bd       = (const float*)d_in[14];

    float* out = (float*)d_out;
    float* ll = out;                         // (SRC,B,TOT)
    float* arc_ll = out + LL_ELEMS;          // (SRC,B,SRC)

    __nv_bfloat16 *cbf = nullptr, *wtbf = nullptr, *hbf = nullptr,
                  *wgbf = nullptr, *lbf = nullptr;
    float *rowsum = nullptr, *graw = nullptr;
    cudaGetSymbolAddress((void**)&cbf,  g_concept_bf);
    cudaGetSymbolAddress((void**)&wtbf, g_Wt_bf);
    cudaGetSymbolAddress((void**)&hbf,  g_h_bf);
    cudaGetSymbolAddress((void**)&wgbf, g_Wg_bf);
    cudaGetSymbolAddress((void**)&lbf,  g_logit_bf);
    cudaGetSymbolAddress((void**)&rowsum, g_rowsum);
    cudaGetSymbolAddress((void**)&graw, g_graw);

    cudaFuncSetAttribute(gemm1_mma_kernel,
                         cudaFuncAttributeMaxDynamicSharedMemorySize, GEMM_SMEM);
    cudaFuncSetAttribute(gemm2_mma_kernel,
                         cudaFuncAttributeMaxDynamicSharedMemorySize, GEMM_SMEM);

    // 0) zero accumulators + fused conversions to bf16
    cudaMemsetAsync(rowsum, 0, M_ROWS * sizeof(float));
    cudaMemsetAsync(graw, 0, M_ROWS * 3 * sizeof(float));
    {
        int n1 = M_ROWS * E_DIM / 4;
        int n2 = C_DIM * E_DIM / 4;
        int n3 = V_DIM * C_DIM / 4;
        int ntot = n1 + n2 + n3;
        convert_all_kernel<<<(ntot + 255) / 256, 256>>>(
            (const float4*)concept, (uint2*)cbf, n1,
            (const float4*)Wt, (uint2*)wtbf, n2,
            (const float4*)Wg, (uint2*)wgbf, n3);
    }

    // 1) h = tanh(concept @ Wt^T + bt) -> bf16, + gate partials
    {
        dim3 grid(C_DIM / 128, M_ROWS / 128);
        gemm1_mma_kernel<<<grid, 256, GEMM_SMEM>>>(cbf, wtbf, bt, hbf, Wd, graw);
    }

    // 2) logits (bf16, coalesced) + exp row sums
    {
        dim3 grid((V_DIM + 127) / 128, M_ROWS / 128);
        gemm2_mma_kernel<<<grid, 256, GEMM_SMEM>>>(hbf, wgbf, bg, lbf, rowsum);
    }

    // 3) finalize: single pass, 1024 thr, streaming stores
    {
        int smem = TOT_DIM * sizeof(float);  // 50000 B
        cudaFuncSetAttribute(finalize_kernel,
                             cudaFuncAttributeMaxDynamicSharedMemorySize, smem);
        finalize_kernel<<<M_ROWS, FTHREADS, smem>>>(ll, lbf, align, copy_seq, bd);
    }

    // 4) arc_ll
    {
        int n4 = (SRC_LEN * BSZ * SRC_LEN) / 4;
        arc_log_kernel<<<(n4 + 255) / 256, 256>>>((const float4*)arc,
                                                  (float4*)arc_ll, n4);
    }
}

// round 17
// speedup vs baseline: 1.1133x; 1.0516x over previous
#include <cuda_runtime.h>
#include <cuda_bf16.h>
#include <math.h>
#include <stdint.h>

// Problem constants (fixed shapes)
#define SRC_LEN 512
#define BSZ     16
#define SNT_LEN 512
#define E_DIM   512
#define C_DIM   512
#define V_DIM   12000
#define EXT_DIM 500
#define TOT_DIM (V_DIM + EXT_DIM)       // 12500
#define M_ROWS  (SRC_LEN * BSZ)         // 8192
#define LL_ELEMS ((size_t)M_ROWS * TOT_DIM)
#define LOG_EPS (-27.6310211159f)       // log(1e-12)

// Scratch (device globals — no allocations allowed)
__device__ __nv_bfloat16 g_concept_bf[(size_t)M_ROWS * E_DIM];
__device__ __nv_bfloat16 g_Wt_bf[(size_t)C_DIM * E_DIM];
__device__ __nv_bfloat16 g_h_bf[(size_t)M_ROWS * C_DIM];
__device__ __nv_bfloat16 g_Wg_bf[(size_t)V_DIM * C_DIM];
__device__ __nv_bfloat16 g_logit_bf[(size_t)M_ROWS * V_DIM];  // bf16 logits
__device__ float g_graw[M_ROWS * 3];    // raw gate logits (pre-softmax, no bias)
__device__ float g_rowsum[M_ROWS];      // sum of exp(logits) per row

#define GK   512
#define BK   64
#define NKT  (GK / BK)            // 8
#define ROWB 144                  // padded smem row stride (bytes)
#define STAGE_BYTES (128 * ROWB)  // 18432 per operand per stage
#define NSTAGE 3
#define GEMM_SMEM (NSTAGE * 2 * STAGE_BYTES)   // 110592
#define ROWB_STG 272              // epilogue staging stride (17*16)

#define V4   (V_DIM / 4)      // 3000
#define T4   (TOT_DIM / 4)    // 3125
#define V8   (V_DIM / 8)      // 1500

__device__ __forceinline__ uint32_t smem_u32(const void* p) {
    uint32_t a;
    asm("{ .reg .u64 t; cvta.to.shared.u64 t, %1; cvt.u32.u64 %0, t; }"
        : "=r"(a) : "l"(p));
    return a;
}
__device__ __forceinline__ void cp16(uint32_t saddr, const void* gaddr, uint32_t srcsz) {
    asm volatile("cp.async.cg.shared.global [%0], [%1], 16, %2;"
                 :: "r"(saddr), "l"(gaddr), "r"(srcsz));
}
__device__ __forceinline__ void cp_commit() {
    asm volatile("cp.async.commit_group;");
}
template <int N>
__device__ __forceinline__ void cp_wait() {
    asm volatile("cp.async.wait_group %0;" :: "n"(N));
}
__device__ __forceinline__ void ldmx4(uint32_t addr, uint32_t& r0, uint32_t& r1,
                                      uint32_t& r2, uint32_t& r3) {
    asm volatile("ldmatrix.sync.aligned.m8n8.x4.shared.b16 {%0,%1,%2,%3}, [%4];"
                 : "=r"(r0), "=r"(r1), "=r"(r2), "=r"(r3) : "r"(addr));
}
__device__ __forceinline__ void mma16816(float& c0, float& c1, float& c2, float& c3,
                                         uint32_t a0, uint32_t a1, uint32_t a2, uint32_t a3,
                                         uint32_t b0, uint32_t b1) {
    asm volatile(
        "mma.sync.aligned.m16n8k16.row.col.f32.bf16.bf16.f32 "
        "{%0,%1,%2,%3}, {%4,%5,%6,%7}, {%8,%9}, {%0,%1,%2,%3};"
        : "+f"(c0), "+f"(c1), "+f"(c2), "+f"(c3)
        : "r"(a0), "r"(a1), "r"(a2), "r"(a3), "r"(b0), "r"(b1));
}
__device__ __forceinline__ float tanh_fast(float x) {
    float y;
    asm("tanh.approx.f32 %0, %1;" : "=f"(y) : "f"(x));
    return y;
}

// ===========================================================================
// shared mainloop body (128x128, 256 thr)
// ===========================================================================
#define GEMM_MAINLOOP(A_, B_, NGUARD)                                          \
    auto a_off = [&](int s) -> uint32_t { return sbase + s * 2 * STAGE_BYTES; };\
    auto b_off = [&](int s) -> uint32_t { return sbase + s * 2 * STAGE_BYTES + STAGE_BYTES; };\
    auto issue_stage = [&](int kt, int s) {                                    \
        const int k0 = kt * BK;                                                \
        _Pragma("unroll")                                                      \
        for (int u = 0; u < 4; u++) {                                          \
            int idx = tid + u * 256;                                           \
            int row = idx >> 3;                                                \
            int c   = idx & 7;                                                 \
            cp16(a_off(s) + row * ROWB + c * 16,                               \
                 A_ + (size_t)(m0 + row) * GK + k0 + c * 8, 16);               \
        }                                                                      \
        _Pragma("unroll")                                                      \
        for (int u = 0; u < 4; u++) {                                          \
            int idx = tid + u * 256;                                           \
            int row = idx >> 3;                                                \
            int c   = idx & 7;                                                 \
            int gr = n0 + row;                                                 \
            const void* ga = B_ + (size_t)(gr < NGUARD ? gr : NGUARD - 1) * GK + k0 + c * 8;\
            cp16(b_off(s) + row * ROWB + c * 16, ga, (gr < NGUARD) ? 16u : 0u);\
        }                                                                      \
        cp_commit();                                                           \
    };                                                                         \
    float acc[4][4][4];                                                        \
    _Pragma("unroll")                                                          \
    for (int i = 0; i < 4; i++)                                                \
        _Pragma("unroll")                                                      \
        for (int j = 0; j < 4; j++)                                            \
            _Pragma("unroll")                                                  \
            for (int e = 0; e < 4; e++) acc[i][j][e] = 0.f;                    \
    issue_stage(0, 0);                                                         \
    issue_stage(1, 1);                                                         \
    const int g    = lane >> 3;                                                \
    const int lrow = lane & 7;                                                 \
    _Pragma("unroll")                                                          \
    for (int kt = 0; kt < NKT; kt++) {                                         \
        const int s = kt % NSTAGE;                                             \
        if (kt + 2 < NKT) {                                                    \
            issue_stage(kt + 2, (kt + 2) % NSTAGE);                            \
            cp_wait<2>();                                                      \
        } else if (kt + 1 < NKT) {                                             \
            cp_wait<1>();                                                      \
        } else {                                                               \
            cp_wait<0>();                                                      \
        }                                                                      \
        __syncthreads();                                                       \
        const uint32_t abase = a_off(s);                                       \
        const uint32_t bbase = b_off(s);                                       \
        _Pragma("unroll")                                                      \
        for (int ks = 0; ks < 4; ks++) {                                       \
            uint32_t a[4][4];                                                  \
            _Pragma("unroll")                                                  \
            for (int mt = 0; mt < 4; mt++) {                                   \
                int row = warp_m * 64 + mt * 16 + lrow + (g & 1) * 8;          \
                int chunk = ks * 2 + (g >> 1);                                 \
                ldmx4(abase + row * ROWB + chunk * 16,                         \
                      a[mt][0], a[mt][1], a[mt][2], a[mt][3]);                 \
            }                                                                  \
            uint32_t b[4][2];                                                  \
            _Pragma("unroll")                                                  \
            for (int nt = 0; nt < 2; nt++) {                                   \
                int row = warp_n * 32 + nt * 16 + lrow + (g >> 1) * 8;         \
                int chunk = ks * 2 + (g & 1);                                  \
                uint32_t r0, r1, r2, r3;                                       \
                ldmx4(bbase + row * ROWB + chunk * 16, r0, r1, r2, r3);        \
                b[nt * 2 + 0][0] = r0; b[nt * 2 + 0][1] = r1;                  \
                b[nt * 2 + 1][0] = r2; b[nt * 2 + 1][1] = r3;                  \
            }                                                                  \
            _Pragma("unroll")                                                  \
            for (int mt = 0; mt < 4; mt++)                                     \
                _Pragma("unroll")                                              \
                for (int nt = 0; nt < 4; nt++)                                 \
                    mma16816(acc[mt][nt][0], acc[mt][nt][1],                   \
                             acc[mt][nt][2], acc[mt][nt][3],                   \
                             a[mt][0], a[mt][1], a[mt][2], a[mt][3],           \
                             b[nt][0], b[nt][1]);                              \
        }                                                                      \
        __syncthreads();                                                       \
    }

// ===========================================================================
// GEMM1: h = tanh(concept @ Wt^T + bt) -> bf16, + gate partial dots into graw.
// ===========================================================================
__global__ __launch_bounds__(256, 2) void gemm1_mma_kernel(
    const __nv_bfloat16* __restrict__ A,
    const __nv_bfloat16* __restrict__ B,
    const float* __restrict__ bias,
    __nv_bfloat16* __restrict__ Cb,
    const float* __restrict__ Wdiv,
    float* __restrict__ graw)
{
    extern __shared__ char smem[];
    const uint32_t sbase = smem_u32(smem);
    const int tid  = threadIdx.x;
    const int wid  = tid >> 5;
    const int lane = tid & 31;
    const int m0 = blockIdx.y * 128;
    const int n0 = blockIdx.x * 128;
    const int warp_m = wid & 1;
    const int warp_n = wid >> 1;

    GEMM_MAINLOOP(A, B, C_DIM)

    const int trow = lane >> 2;
    const int tcol = (lane & 3) * 2;
#pragma unroll
    for (int mt = 0; mt < 4; mt++) {
        const int gm = m0 + warp_m * 64 + mt * 16 + trow;
        float p0[3] = {0.f, 0.f, 0.f};
        float p1[3] = {0.f, 0.f, 0.f};
#pragma unroll
        for (int nt = 0; nt < 4; nt++) {
            int gn = n0 + warp_n * 32 + nt * 8 + tcol;
            float2 bv = *reinterpret_cast<const float2*>(bias + gn);
            float t0x = tanh_fast(acc[mt][nt][0] + bv.x);
            float t0y = tanh_fast(acc[mt][nt][1] + bv.y);
            float t1x = tanh_fast(acc[mt][nt][2] + bv.x);
            float t1y = tanh_fast(acc[mt][nt][3] + bv.y);
            *reinterpret_cast<__nv_bfloat162*>(Cb + (size_t)gm * C_DIM + gn) =
                __floats2bfloat162_rn(t0x, t0y);
            *reinterpret_cast<__nv_bfloat162*>(Cb + (size_t)(gm + 8) * C_DIM + gn) =
                __floats2bfloat162_rn(t1x, t1y);
#pragma unroll
            for (int j = 0; j < 3; j++) {
                float2 w = *reinterpret_cast<const float2*>(Wdiv + j * C_DIM + gn);
                p0[j] = fmaf(w.x, t0x, fmaf(w.y, t0y, p0[j]));
                p1[j] = fmaf(w.x, t1x, fmaf(w.y, t1y, p1[j]));
            }
        }
#pragma unroll
        for (int j = 0; j < 3; j++) {
            p0[j] += __shfl_xor_sync(0xffffffffu, p0[j], 1);
            p0[j] += __shfl_xor_sync(0xffffffffu, p0[j], 2);
            p1[j] += __shfl_xor_sync(0xffffffffu, p1[j], 1);
            p1[j] += __shfl_xor_sync(0xffffffffu, p1[j], 2);
        }
        if ((lane & 3) == 0) {
#pragma unroll
            for (int j = 0; j < 3; j++) {
                atomicAdd(&graw[gm * 3 + j], p0[j]);
                atomicAdd(&graw[(gm + 8) * 3 + j], p1[j]);
            }
        }
    }
}

// ===========================================================================
// GEMM2: bf16 logits (coalesced via smem staging) + exp row sums.
// ===========================================================================
__global__ __launch_bounds__(256, 2) void gemm2_mma_kernel(
    const __nv_bfloat16* __restrict__ A,
    const __nv_bfloat16* __restrict__ B,
    const float* __restrict__ bias,
    __nv_bfloat16* __restrict__ Cb,
    float* __restrict__ rowsum)
{
    extern __shared__ char smem[];
    const uint32_t sbase = smem_u32(smem);
    const int tid  = threadIdx.x;
    const int wid  = tid >> 5;
    const int lane = tid & 31;
    const int m0 = blockIdx.y * 128;
    const int n0 = blockIdx.x * 128;
    const int warp_m = wid & 1;
    const int warp_n = wid >> 1;

    GEMM_MAINLOOP(A, B, V_DIM)

    // ---- epilogue: exp rowsums + stage bf16 tile in smem ----
    const int trow = lane >> 2;
    const int tcol = (lane & 3) * 2;
#pragma unroll
    for (int mt = 0; mt < 4; mt++) {
        const int gm = m0 + warp_m * 64 + mt * 16 + trow;
        const int srow = warp_m * 64 + mt * 16 + trow;
        float rs0 = 0.f, rs1 = 0.f;
#pragma unroll
        for (int nt = 0; nt < 4; nt++) {
            int gn = n0 + warp_n * 32 + nt * 8 + tcol;
            int scol = warp_n * 32 + nt * 8 + tcol;
            float l0 = 0.f, l1 = 0.f, l2 = 0.f, l3 = 0.f;
            if (gn < V_DIM) {
                float2 bv = *reinterpret_cast<const float2*>(bias + gn);
                l0 = acc[mt][nt][0] + bv.x;
                l1 = acc[mt][nt][1] + bv.y;
                l2 = acc[mt][nt][2] + bv.x;
                l3 = acc[mt][nt][3] + bv.y;
                rs0 += __expf(l0) + __expf(l1);
                rs1 += __expf(l2) + __expf(l3);
            }
            *reinterpret_cast<__nv_bfloat162*>(smem + srow * ROWB_STG + scol * 2) =
                __floats2bfloat162_rn(l0, l1);
            *reinterpret_cast<__nv_bfloat162*>(smem + (srow + 8) * ROWB_STG + scol * 2) =
                __floats2bfloat162_rn(l2, l3);
        }
        rs0 += __shfl_xor_sync(0xffffffffu, rs0, 1);
        rs0 += __shfl_xor_sync(0xffffffffu, rs0, 2);
        rs1 += __shfl_xor_sync(0xffffffffu, rs1, 1);
        rs1 += __shfl_xor_sync(0xffffffffu, rs1, 2);
        if ((lane & 3) == 0) {
            atomicAdd(&rowsum[gm], rs0);
            atomicAdd(&rowsum[gm + 8], rs1);
        }
    }
    __syncthreads();

    // ---- coalesced bf16 writes: 16B per thread, contiguous runs ----
#pragma unroll
    for (int u = 0; u < 8; u++) {
        int idx = tid + u * 256;
        int row = idx >> 4;
        int chunk = idx & 15;
        int gn0 = n0 + chunk * 8;
        if (gn0 < V_DIM) {
            uint4 v = *reinterpret_cast<const uint4*>(smem + row * ROWB_STG + chunk * 16);
            *reinterpret_cast<uint4*>(Cb + (size_t)(m0 + row) * V_DIM + gn0) = v;
        }
    }
}

// ===========================================================================
// fused fp32 -> bf16 conversion (concept, Wt, Wg in one launch)
// ===========================================================================
__global__ __launch_bounds__(256) void convert_all_kernel(
    const float4* __restrict__ c,  uint2* __restrict__ co, int n1,
    const float4* __restrict__ wt, uint2* __restrict__ wo, int n2,
    const float4* __restrict__ wg, uint2* __restrict__ go, int n3)
{
    int i = blockIdx.x * blockDim.x + threadIdx.x;
    const float4* src;
    uint2* dst;
    int j = i;
    if (j < n1) { src = c; dst = co; }
    else {
        j -= n1;
        if (j < n2) { src = wt; dst = wo; }
        else {
            j -= n2;
            if (j >= n3) return;
            src = wg; dst = go;
        }
    }
    float4 v = src[j];
    __nv_bfloat162 lo = __floats2bfloat162_rn(v.x, v.y);
    __nv_bfloat162 hi = __floats2bfloat162_rn(v.z, v.w);
    uint2 o;
    o.x = *reinterpret_cast<uint32_t*>(&lo);
    o.y = *reinterpret_cast<uint32_t*>(&hi);
    dst[j] = o;
}

// ===========================================================================
// finalize (single pass, R14 config): gates softmax3 inline;
// scale = gen/rowsum; K = log(scale).
// non-scattered: ll = logit + K.  scattered: __logf(__expf(l)*scale+sc+eps).
// ===========================================================================
__global__ __launch_bounds__(512) void finalize_kernel(
    float* __restrict__ out,
    const __nv_bfloat16* __restrict__ Lb,   // (M_ROWS, V_DIM) bf16 logits
    const float* __restrict__ align,        // (SRC, B, SNT)
    const int*   __restrict__ copy_seq,     // (SNT, B, 2)
    const float* __restrict__ bdiv)
{
    extern __shared__ __align__(16) float scat[];   // TOT_DIM floats

    const int r = blockIdx.x;
    const int b = r & (BSZ - 1);
    const int tid = threadIdx.x;
    float4* out4 = reinterpret_cast<float4*>(out + (size_t)r * TOT_DIM);
    const uint4* lrow = reinterpret_cast<const uint4*>(Lb + (size_t)r * V_DIM);
    float4* scat4 = reinterpret_cast<float4*>(scat);

    // gates softmax3 (redundant per thread, trivial)
    float s0 = g_graw[r * 3 + 0] + bdiv[0];
    float s1 = g_graw[r * 3 + 1] + bdiv[1];
    float s2 = g_graw[r * 3 + 2] + bdiv[2];
    float mx = fmaxf(s0, fmaxf(s1, s2));
    float e0 = __expf(s0 - mx), e1 = __expf(s1 - mx), e2 = __expf(s2 - mx);
    float inv = 1.f / (e0 + e1 + e2);
    const float gen = e0 * inv;
    const float mp  = e1 * inv;   // map gate (gates[...,1])
    const float cpy = e2 * inv;   // copy gate (gates[...,2])
    const float scale = gen / g_rowsum[r];
    const float K = logf(scale);

    // zero scatter buffer
    for (int c = tid; c < T4; c += 512)
        scat4[c] = make_float4(0.f, 0.f, 0.f, 0.f);
    __syncthreads();

    // scatter-add 1024 copy probabilities into smem
    const float* arow = align + (size_t)r * SNT_LEN;
    for (int j = tid; j < 2 * SNT_LEN; j += 512) {
        int snt = j >> 1;
        int k = j & 1;
        int idx = copy_seq[((size_t)snt * BSZ + b) * 2 + k];
        float v = (k == 0 ? cpy : mp) * arow[snt];
        if (idx >= 0 && idx < TOT_DIM) atomicAdd(&scat[idx], v);
    }
    __syncthreads();

    // vocab region: 8 bf16 logits per uint4 (fast-math predicated paths)
    for (int c = tid; c < V8; c += 512) {
        uint4 p = lrow[c];
        float l[8];
        {
            const uint32_t* w = &p.x;
#pragma unroll
            for (int i = 0; i < 4; i++) {
                float2 f = __bfloat1622float2(
                    *reinterpret_cast<const __nv_bfloat162*>(&w[i]));
                l[i * 2] = f.x; l[i * 2 + 1] = f.y;
            }
        }
        float4 sc0 = scat4[2 * c];
        float4 sc1 = scat4[2 * c + 1];
        float4 o0, o1;
        o0.x = (sc0.x > 0.f) ? __logf(__expf(l[0]) * scale + sc0.x + 1e-12f) : l[0] + K;
        o0.y = (sc0.y > 0.f) ? __logf(__expf(l[1]) * scale + sc0.y + 1e-12f) : l[1] + K;
        o0.z = (sc0.z > 0.f) ? __logf(__expf(l[2]) * scale + sc0.z + 1e-12f) : l[2] + K;
        o0.w = (sc0.w > 0.f) ? __logf(__expf(l[3]) * scale + sc0.w + 1e-12f) : l[3] + K;
        o1.x = (sc1.x > 0.f) ? __logf(__expf(l[4]) * scale + sc1.x + 1e-12f) : l[4] + K;
        o1.y = (sc1.y > 0.f) ? __logf(__expf(l[5]) * scale + sc1.y + 1e-12f) : l[5] + K;
        o1.z = (sc1.z > 0.f) ? __logf(__expf(l[6]) * scale + sc1.z + 1e-12f) : l[6] + K;
        o1.w = (sc1.w > 0.f) ? __logf(__expf(l[7]) * scale + sc1.w + 1e-12f) : l[7] + K;
        out4[2 * c] = o0;
        out4[2 * c + 1] = o1;
    }
    // ext region
    for (int c = V4 + tid; c < T4; c += 512) {
        float4 sc = scat4[c];
        float4 o;
        o.x = (sc.x > 0.f) ? __logf(sc.x + 1e-12f) : LOG_EPS;
        o.y = (sc.y > 0.f) ? __logf(sc.y + 1e-12f) : LOG_EPS;
        o.z = (sc.z > 0.f) ? __logf(sc.z + 1e-12f) : LOG_EPS;
        o.w = (sc.w > 0.f) ? __logf(sc.w + 1e-12f) : LOG_EPS;
        out4[c] = o;
    }
}

// ===========================================================================
// arc_ll = log(arc + 1e-12)  (fast MUFU log)
// ===========================================================================
__global__ __launch_bounds__(256) void arc_log_kernel(
    const float4* __restrict__ in, float4* __restrict__ out, int n4)
{
    int i = blockIdx.x * blockDim.x + threadIdx.x;
    if (i < n4) {
        float4 v = in[i];
        v.x = __logf(v.x + 1e-12f);
        v.y = __logf(v.y + 1e-12f);
        v.z = __logf(v.z + 1e-12f);
        v.w = __logf(v.w + 1e-12f);
        out[i] = v;
    }
}

// ===========================================================================
extern "C" void kernel_launch(void* const* d_in, const int* in_sizes, int n_in,
                              void* d_out, int out_size)
{
    const float* align    = (const float*)d_in[0];
    const float* arc      = (const float*)d_in[1];
    const float* concept  = (const float*)d_in[3];
    const int*   copy_seq = (const int*)  d_in[4];
    const float* Wt       = (const float*)d_in[9];
    const float* bt       = (const float*)d_in[10];
    const float* Wg       = (const float*)d_in[11];
    const float* bg       = (const float*)d_in[12];
    const float* Wd       = (const float*)d_in[13];
    const float* bd       = (const float*)d_in[14];

    float* out = (float*)d_out;
    float* ll = out;                         // (SRC,B,TOT)
    float* arc_ll = out + LL_ELEMS;          // (SRC,B,SRC)

    __nv_bfloat16 *cbf = nullptr, *wtbf = nullptr, *hbf = nullptr,
                  *wgbf = nullptr, *lbf = nullptr;
    float *rowsum = nullptr, *graw = nullptr;
    cudaGetSymbolAddress((void**)&cbf,  g_concept_bf);
    cudaGetSymbolAddress((void**)&wtbf, g_Wt_bf);
    cudaGetSymbolAddress((void**)&hbf,  g_h_bf);
    cudaGetSymbolAddress((void**)&wgbf, g_Wg_bf);
    cudaGetSymbolAddress((void**)&lbf,  g_logit_bf);
    cudaGetSymbolAddress((void**)&rowsum, g_rowsum);
    cudaGetSymbolAddress((void**)&graw, g_graw);

    cudaFuncSetAttribute(gemm1_mma_kernel,
                         cudaFuncAttributeMaxDynamicSharedMemorySize, GEMM_SMEM);
    cudaFuncSetAttribute(gemm2_mma_kernel,
                         cudaFuncAttributeMaxDynamicSharedMemorySize, GEMM_SMEM);

    // 0) zero accumulators + fused conversions to bf16
    cudaMemsetAsync(rowsum, 0, M_ROWS * sizeof(float));
    cudaMemsetAsync(graw, 0, M_ROWS * 3 * sizeof(float));
    {
        int n1 = M_ROWS * E_DIM / 4;
        int n2 = C_DIM * E_DIM / 4;
        int n3 = V_DIM * C_DIM / 4;
        int ntot = n1 + n2 + n3;
        convert_all_kernel<<<(ntot + 255) / 256, 256>>>(
            (const float4*)concept, (uint2*)cbf, n1,
            (const float4*)Wt, (uint2*)wtbf, n2,
            (const float4*)Wg, (uint2*)wgbf, n3);
    }

    // 1) h = tanh(concept @ Wt^T + bt) -> bf16, + gate partials
    {
        dim3 grid(C_DIM / 128, M_ROWS / 128);
        gemm1_mma_kernel<<<grid, 256, GEMM_SMEM>>>(cbf, wtbf, bt, hbf, Wd, graw);
    }

    // 2) logits (bf16, coalesced) + exp row sums
    {
        dim3 grid((V_DIM + 127) / 128, M_ROWS / 128);
        gemm2_mma_kernel<<<grid, 256, GEMM_SMEM>>>(hbf, wgbf, bg, lbf, rowsum);
    }

    // 3) finalize: single pass, gates inline, fast-math predicated paths
    {
        int smem = TOT_DIM * sizeof(float);  // 50000 B
        cudaFuncSetAttribute(finalize_kernel,
                             cudaFuncAttributeMaxDynamicSharedMemorySize, smem);
        finalize_kernel<<<M_ROWS, 512, smem>>>(ll, lbf, align, copy_seq, bd);
    }

    // 4) arc_ll
    {
        int n4 = (SRC_LEN * BSZ * SRC_LEN) / 4;
        arc_log_kernel<<<(n4 + 255) / 256, 256>>>((const float4*)arc,
                                                  (float4*)arc_ll, n4);
    }
}